// round 15
// baseline (speedup 1.0000x reference)
#include <cuda_runtime.h>
#include <cuda_fp16.h>
#include <cstdint>
#include <math.h>

#define NB 2
#define SEQ 2048
#define EDIM 1024
#define NH 16
#define DH 64
#define XSZ (NB * SEQ * EDIM)
#define WSZ (EDIM * EDIM)

// half-converted inputs/weights, projections in [N,H,S,D], V column means, float pad mask.
__device__ __align__(16) __half g_xh[3 * XSZ];
__device__ __align__(16) __half g_wh[3 * WSZ];
__device__ __align__(16) __half g_qh[NB * NH * SEQ * DH];
__device__ __align__(16) __half g_kh[NB * NH * SEQ * DH];
__device__ __align__(16) __half g_vh[NB * NH * SEQ * DH];
__device__ float g_vsum[NB * NH * DH];
__device__ __align__(16) float g_padf[NB * SEQ];

// ---------------- PTX helpers ----------------
__device__ __forceinline__ uint32_t smem_u32(const void* p) {
    return (uint32_t)__cvta_generic_to_shared(p);
}
__device__ __forceinline__ void cp16(uint32_t dst, const void* src) {
    asm volatile("cp.async.cg.shared.global [%0], [%1], 16;" :: "r"(dst), "l"(src));
}
__device__ __forceinline__ void cp4(uint32_t dst, const void* src) {
    asm volatile("cp.async.ca.shared.global [%0], [%1], 4;" :: "r"(dst), "l"(src));
}
__device__ __forceinline__ void cp_commit() { asm volatile("cp.async.commit_group;"); }
template <int N>
__device__ __forceinline__ void cp_wait() { asm volatile("cp.async.wait_group %0;" :: "n"(N)); }

__device__ __forceinline__ void ldsm_x4(uint32_t& r0, uint32_t& r1, uint32_t& r2, uint32_t& r3,
                                        uint32_t addr) {
    asm volatile("ldmatrix.sync.aligned.m8n8.x4.shared.b16 {%0,%1,%2,%3}, [%4];"
                 : "=r"(r0), "=r"(r1), "=r"(r2), "=r"(r3) : "r"(addr));
}
__device__ __forceinline__ void ldsm_x4_t(uint32_t& r0, uint32_t& r1, uint32_t& r2, uint32_t& r3,
                                          uint32_t addr) {
    asm volatile("ldmatrix.sync.aligned.m8n8.x4.trans.shared.b16 {%0,%1,%2,%3}, [%4];"
                 : "=r"(r0), "=r"(r1), "=r"(r2), "=r"(r3) : "r"(addr));
}
__device__ __forceinline__ void mma_16816(float* c, const uint32_t* a, uint32_t b0, uint32_t b1) {
    asm volatile(
        "mma.sync.aligned.m16n8k16.row.col.f32.f16.f16.f32 "
        "{%0,%1,%2,%3},{%4,%5,%6,%7},{%8,%9},{%0,%1,%2,%3};"
        : "+f"(c[0]), "+f"(c[1]), "+f"(c[2]), "+f"(c[3])
        : "r"(a[0]), "r"(a[1]), "r"(a[2]), "r"(a[3]), "r"(b0), "r"(b1));
}
__device__ __forceinline__ uint32_t pack_h2(float x, float y) {
    __half2 h = __floats2half2_rn(x, y);
    return *reinterpret_cast<uint32_t*>(&h);
}
__device__ __forceinline__ float ex2f(float x) {
    float y;
    asm("ex2.approx.ftz.f32 %0, %1;" : "=f"(y) : "f"(x));
    return y;
}

#define QSCALE (0.125f * 1.44269504f)  // 1/sqrt(64) * log2(e), folded into Wq/bq

// ---------------- fp32 -> fp16 conversion (X, W; Wq folds scale); pad -> float ----------------
__global__ void cvt_kernel(const float* __restrict__ q, const float* __restrict__ k,
                           const float* __restrict__ v, const float* __restrict__ Wq,
                           const float* __restrict__ Wk, const float* __restrict__ Wv,
                           const int* __restrict__ pad) {
    const int y = blockIdx.y;
    if (y == 6) {
        for (int i = blockIdx.x * blockDim.x + threadIdx.x; i < NB * SEQ;
             i += gridDim.x * blockDim.x)
            g_padf[i] = pad[i] ? 1.0f : 0.0f;
        return;
    }
    const float* src;
    __half* dst;
    int n4;
    float sc = 1.0f;
    switch (y) {
        case 0: src = q;  dst = g_xh;           n4 = XSZ / 4; break;
        case 1: src = k;  dst = g_xh + XSZ;     n4 = XSZ / 4; break;
        case 2: src = v;  dst = g_xh + 2 * XSZ; n4 = XSZ / 4; break;
        case 3: src = Wq; dst = g_wh;           n4 = WSZ / 4; sc = QSCALE; break;
        case 4: src = Wk; dst = g_wh + WSZ;     n4 = WSZ / 4; break;
        default: src = Wv; dst = g_wh + 2 * WSZ; n4 = WSZ / 4; break;
    }
    for (int i = blockIdx.x * blockDim.x + threadIdx.x; i < n4; i += gridDim.x * blockDim.x) {
        float4 f = ((const float4*)src)[i];
        __half2 h0 = __floats2half2_rn(f.x * sc, f.y * sc);
        __half2 h1 = __floats2half2_rn(f.z * sc, f.w * sc);
        uint2 u;
        u.x = *(uint32_t*)&h0;
        u.y = *(uint32_t*)&h1;
        ((uint2*)dst)[i] = u;
    }
}

// ---------------- QKV projection GEMM (half in, cp.async double-buffered) ----------------
__global__ __launch_bounds__(256, 2) void qkv_proj_kernel(
    const float* __restrict__ bq, const float* __restrict__ bk, const float* __restrict__ bv)
{
    const int z = blockIdx.z;
    const __half* X   = g_xh + (size_t)z * XSZ;
    const __half* W   = g_wh + (size_t)z * WSZ;
    const float* bias = (z == 0) ? bq : (z == 1) ? bk : bv;
    __half* Out       = (z == 0) ? g_qh : (z == 1) ? g_kh : g_vh;
    const float wsc   = (z == 0) ? QSCALE : 1.0f;

    __shared__ __align__(16) __half As[2][128][72];
    __shared__ __align__(16) __half Bs[2][128][72];

    const int tid = threadIdx.x, lane = tid & 31, wid = tid >> 5;
    const int wm = wid >> 2;
    const int wn = wid & 3;
    const int bm = blockIdx.x * 128;
    const int bn = blockIdx.y * 128;

    float c[4][4][4] = {};

#define QKV_LOAD(buf, k0)                                                            \
    {                                                                                \
        _Pragma("unroll") for (int i = 0; i < 4; i++) {                              \
            int cid = i * 256 + tid;                                                 \
            int r = cid >> 3, c8 = cid & 7;                                          \
            cp16(smem_u32(&As[buf][r][c8 * 8]),                                      \
                 X + (size_t)(bm + r) * EDIM + (k0) + c8 * 8);                       \
            cp16(smem_u32(&Bs[buf][r][c8 * 8]),                                      \
                 W + (size_t)(bn + r) * EDIM + (k0) + c8 * 8);                       \
        }                                                                            \
    }

    QKV_LOAD(0, 0);
    cp_commit();

    int cur = 0;
    for (int k0 = 0; k0 < EDIM; k0 += 64) {
        cp_wait<0>();
        __syncthreads();
        if (k0 + 64 < EDIM) {
            QKV_LOAD(cur ^ 1, k0 + 64);
            cp_commit();
        }

#pragma unroll
        for (int ks = 0; ks < 4; ks++) {
            uint32_t af[4][4], bf[2][4];
#pragma unroll
            for (int mi = 0; mi < 4; mi++) {
                uint32_t a = smem_u32(&As[cur][wm * 64 + mi * 16 + (lane & 15)]
                                            [ks * 16 + ((lane >> 4) & 1) * 8]);
                ldsm_x4(af[mi][0], af[mi][1], af[mi][2], af[mi][3], a);
            }
#pragma unroll
            for (int np = 0; np < 2; np++) {
                int nr = wn * 32 + np * 16 + (lane & 7) + ((lane >> 4) & 1) * 8;
                int nc = ks * 16 + ((lane >> 3) & 1) * 8;
                uint32_t a = smem_u32(&Bs[cur][nr][nc]);
                ldsm_x4(bf[np][0], bf[np][1], bf[np][2], bf[np][3], a);
            }
#pragma unroll
            for (int mi = 0; mi < 4; mi++)
#pragma unroll
                for (int ni = 0; ni < 4; ni++)
                    mma_16816(c[mi][ni], af[mi],
                              bf[ni >> 1][(ni & 1) * 2], bf[ni >> 1][(ni & 1) * 2 + 1]);
        }
        cur ^= 1;
    }

    const int g = lane >> 2, t4 = lane & 3;
#pragma unroll
    for (int mi = 0; mi < 4; mi++) {
#pragma unroll
        for (int ni = 0; ni < 4; ni++) {
            int col = bn + wn * 32 + ni * 8 + t4 * 2;
            float b0 = bias[col] * wsc, b1 = bias[col + 1] * wsc;
            int hh = col >> 6, d = col & 63;
#pragma unroll
            for (int hr = 0; hr < 2; hr++) {
                int row = bm + wm * 64 + mi * 16 + g + hr * 8;
                int bb = row >> 11, srow = row & 2047;
                __half2 hv = __floats2half2_rn(c[mi][ni][hr * 2] + b0, c[mi][ni][hr * 2 + 1] + b1);
                *(__half2*)(Out + ((size_t)((bb * NH + hh) * SEQ + srow)) * DH + d) = hv;
            }
        }
    }
}

// ---------------- V column mean (for fully-masked rows) ----------------
__global__ void vsum_kernel() {
    const int bh = blockIdx.x;
    const int rg = threadIdx.x >> 3;
    const int dc = threadIdx.x & 7;
    const __half* p = g_vh + (size_t)bh * SEQ * DH;
    float acc[8] = {};
#pragma unroll 4
    for (int r = rg; r < SEQ; r += 32) {
        uint4 u = *(const uint4*)(p + (size_t)r * DH + dc * 8);
        const __half2* h = (const __half2*)&u;
#pragma unroll
        for (int j = 0; j < 4; j++) {
            float2 f = __half22float2(h[j]);
            acc[2 * j] += f.x;
            acc[2 * j + 1] += f.y;
        }
    }
    __shared__ float red[32][64];
#pragma unroll
    for (int j = 0; j < 8; j++) red[rg][dc * 8 + j] = acc[j];
    __syncthreads();
    if (threadIdx.x < 64) {
        float s = 0.f;
#pragma unroll
        for (int i = 0; i < 32; i++) s += red[i][threadIdx.x];
        g_vsum[bh * DH + threadIdx.x] = s * (1.0f / SEQ);
    }
}

// ---------------- Flash attention (max-free softmax, 4-warp CTAs, greedy-balanced grid) ----------------
// grid (32, H, N), 128 threads (4 warps x 16 rows). Br=64, Bc=64, D=64.
// One row-block per CTA, rb = 31 - blockIdx.x (heavy blocks first). 1024
// variable-work CTAs over 592 slots let the scheduler greedily backfill --
// beats the paired-uniform layout whose 512 CTAs quantize to 4-vs-3 per SM.
// Loop schedule: [wait<0>; sync; issue KV(jb+1); compute jb].
#define NRB64 (SEQ / 64)
__global__ __launch_bounds__(128, 4) void flash_kernel(float* __restrict__ out)
{
    const int h = blockIdx.y, b = blockIdx.z;
    const int tid = threadIdx.x, lane = tid & 31, warp = tid >> 5;
    const int rb = NRB64 - 1 - (int)blockIdx.x;

    const __half* Qg = g_qh + ((size_t)((b * NH + h) * SEQ) + rb * 64) * DH;
    const __half* Kg = g_kh + (size_t)((b * NH + h) * SEQ) * DH;
    const __half* Vg = g_vh + (size_t)((b * NH + h) * SEQ) * DH;
    const float* padf = g_padf + b * SEQ;

    __shared__ __align__(16) __half Qs[64][72];
    __shared__ __align__(16) __half Ks[2][64][72];
    __shared__ __align__(16) __half Vs[2][64][72];
    __shared__ __align__(16) float pads[2][64];

#define FLASH_LOAD_KV(buf, jb)                                                       \
    {                                                                                \
        _Pragma("unroll") for (int i = 0; i < 4; i++) {                              \
            int cid = i * 128 + tid;                                                 \
            int r = cid >> 3, c8 = cid & 7;                                          \
            cp16(smem_u32(&Ks[buf][r][c8 * 8]),                                      \
                 Kg + (size_t)((jb) * 64 + r) * DH + c8 * 8);                        \
            cp16(smem_u32(&Vs[buf][r][c8 * 8]),                                      \
                 Vg + (size_t)((jb) * 64 + r) * DH + c8 * 8);                        \
        }                                                                            \
        if (tid < 64) cp4(smem_u32(&pads[buf][tid]), padf + (jb) * 64 + tid);        \
    }

    const int g = lane >> 2, t4 = lane & 3;

    // prologue: Q tile + KV tile 0, one commit group
#pragma unroll
    for (int i = 0; i < 4; i++) {
        int cid = i * 128 + tid;
        int r = cid >> 3, c8 = cid & 7;
        cp16(smem_u32(&Qs[r][c8 * 8]), Qg + (size_t)r * DH + c8 * 8);
    }
    FLASH_LOAD_KV(0, 0);
    cp_commit();

    uint32_t qf[4][4];
    float of[8][4] = {};
    float l0 = 0.f, l1 = 0.f;
    const int row0 = rb * 64 + warp * 16 + g;
    const int row1 = row0 + 8;
    const int jbmax = rb;

    for (int jb = 0; jb <= jbmax; jb++) {
        const int cur = jb & 1;

        // wait covers the group committed one tile ago (or the prologue)
        cp_wait<0>();
        __syncthreads();
        if (jb < jbmax) {
            FLASH_LOAD_KV(cur ^ 1, jb + 1);
            cp_commit();
        }
        if (jb == 0) {
#pragma unroll
            for (int kk = 0; kk < 4; kk++) {
                uint32_t a = smem_u32(&Qs[warp * 16 + (lane & 15)]
                                         [kk * 16 + ((lane >> 4) & 1) * 8]);
                ldsm_x4(qf[kk][0], qf[kk][1], qf[kk][2], qf[kk][3], a);
            }
        }

        // S = Q K^T
        float sf[8][4] = {};
#pragma unroll
        for (int kk = 0; kk < 4; kk++) {
            uint32_t kb[4][4];
#pragma unroll
            for (int np = 0; np < 4; np++) {
                int nr = np * 16 + (lane & 7) + ((lane >> 4) & 1) * 8;
                int nc = kk * 16 + ((lane >> 3) & 1) * 8;
                uint32_t a = smem_u32(&Ks[cur][nr][nc]);
                ldsm_x4(kb[np][0], kb[np][1], kb[np][2], kb[np][3], a);
            }
#pragma unroll
            for (int nt = 0; nt < 8; nt++)
                mma_16816(sf[nt], qf[kk],
                          kb[nt >> 1][(nt & 1) * 2], kb[nt >> 1][(nt & 1) * 2 + 1]);
        }

        // e = 2^s * pad; causal select only on the diagonal tile
        if (jb == jbmax) {
#pragma unroll
            for (int nt = 0; nt < 8; nt++) {
                int cloc = nt * 8 + t4 * 2;
                int tc = jb * 64 + cloc;
                float2 pp = *(const float2*)&pads[cur][cloc];
                float e0 = (tc     <= row0) ? ex2f(sf[nt][0]) * pp.x : 0.f;
                float e1 = (tc + 1 <= row0) ? ex2f(sf[nt][1]) * pp.y : 0.f;
                float e2 = (tc     <= row1) ? ex2f(sf[nt][2]) * pp.x : 0.f;
                float e3 = (tc + 1 <= row1) ? ex2f(sf[nt][3]) * pp.y : 0.f;
                l0 += e0 + e1; l1 += e2 + e3;
                sf[nt][0] = e0; sf[nt][1] = e1; sf[nt][2] = e2; sf[nt][3] = e3;
            }
        } else {
#pragma unroll
            for (int nt = 0; nt < 8; nt++) {
                int cloc = nt * 8 + t4 * 2;
                float2 pp = *(const float2*)&pads[cur][cloc];
                float e0 = ex2f(sf[nt][0]) * pp.x;
                float e1 = ex2f(sf[nt][1]) * pp.y;
                float e2 = ex2f(sf[nt][2]) * pp.x;
                float e3 = ex2f(sf[nt][3]) * pp.y;
                l0 += e0 + e1; l1 += e2 + e3;
                sf[nt][0] = e0; sf[nt][1] = e1; sf[nt][2] = e2; sf[nt][3] = e3;
            }
        }

        // P as A-fragment (FA2 trick)
        uint32_t pf[4][4];
#pragma unroll
        for (int kk = 0; kk < 4; kk++) {
            pf[kk][0] = pack_h2(sf[2 * kk][0],     sf[2 * kk][1]);
            pf[kk][1] = pack_h2(sf[2 * kk][2],     sf[2 * kk][3]);
            pf[kk][2] = pack_h2(sf[2 * kk + 1][0], sf[2 * kk + 1][1]);
            pf[kk][3] = pack_h2(sf[2 * kk + 1][2], sf[2 * kk + 1][3]);
        }

        // O += P V
#pragma unroll
        for (int kk = 0; kk < 4; kk++) {
            uint32_t vb[4][4];
#pragma unroll
            for (int np = 0; np < 4; np++) {
                int vr = kk * 16 + (lane & 7) + ((lane >> 3) & 1) * 8;
                int vc = np * 16 + ((lane >> 4) & 1) * 8;
                uint32_t a = smem_u32(&Vs[cur][vr][vc]);
                ldsm_x4_t(vb[np][0], vb[np][1], vb[np][2], vb[np][3], a);
            }
#pragma unroll
            for (int nt = 0; nt < 8; nt++)
                mma_16816(of[nt], pf[kk],
                          vb[nt >> 1][(nt & 1) * 2], vb[nt >> 1][(nt & 1) * 2 + 1]);
        }
    }

    l0 += __shfl_xor_sync(0xffffffffu, l0, 1);
    l0 += __shfl_xor_sync(0xffffffffu, l0, 2);
    l1 += __shfl_xor_sync(0xffffffffu, l1, 1);
    l1 += __shfl_xor_sync(0xffffffffu, l1, 2);

    bool fm0 = (l0 == 0.f), fm1 = (l1 == 0.f);  // fully masked row -> uniform over all T
    float inv0 = fm0 ? 0.f : 1.f / l0;
    float inv1 = fm1 ? 0.f : 1.f / l1;
    const float* vs = g_vsum + (b * NH + h) * DH;
#pragma unroll
    for (int nt = 0; nt < 8; nt++) {
        int d = nt * 8 + t4 * 2;
        float o0 = of[nt][0] * inv0, o1 = of[nt][1] * inv0;
        float o2 = of[nt][2] * inv1, o3 = of[nt][3] * inv1;
        if (fm0) { o0 = vs[d]; o1 = vs[d + 1]; }
        if (fm1) { o2 = vs[d]; o3 = vs[d + 1]; }
        size_t base0 = ((size_t)b * SEQ + row0) * EDIM + h * DH + d;
        size_t base1 = ((size_t)b * SEQ + row1) * EDIM + h * DH + d;
        *(float2*)(out + base0) = make_float2(o0, o1);
        *(float2*)(out + base1) = make_float2(o2, o3);
    }
}

// ---------------- launch ----------------
extern "C" void kernel_launch(void* const* d_in, const int* in_sizes, int n_in,
                              void* d_out, int out_size) {
    const float* query = (const float*)d_in[0];
    const float* key   = (const float*)d_in[1];
    const float* value = (const float*)d_in[2];
    const int*   pad   = (const int*)d_in[3];
    // d_in[4] = subsq_mask (tril) -> implemented as causal predicate
    const float* Wq = (const float*)d_in[5];
    const float* bq = (const float*)d_in[6];
    const float* Wk = (const float*)d_in[7];
    const float* bk = (const float*)d_in[8];
    const float* Wv = (const float*)d_in[9];
    const float* bv = (const float*)d_in[10];
    float* out = (float*)d_out;

    cvt_kernel<<<dim3(512, 7), 256>>>(query, key, value, Wq, Wk, Wv, pad);
    qkv_proj_kernel<<<dim3(32, 8, 3), 256>>>(bq, bk, bv);
    vsum_kernel<<<NB * NH, 256>>>();
    flash_kernel<<<dim3(NRB64, NH, NB), 128>>>(out);
}

// round 17
// speedup vs baseline: 1.0698x; 1.0698x over previous
#include <cuda_runtime.h>
#include <cuda_fp16.h>
#include <cstdint>
#include <math.h>

#define NB 2
#define SEQ 2048
#define EDIM 1024
#define NH 16
#define DH 64
#define XSZ (NB * SEQ * EDIM)
#define WSZ (EDIM * EDIM)

// half-converted inputs/weights, projections in [N,H,S,D], V column means, float pad mask.
__device__ __align__(16) __half g_xh[3 * XSZ];
__device__ __align__(16) __half g_wh[3 * WSZ];
__device__ __align__(16) __half g_qh[NB * NH * SEQ * DH];
__device__ __align__(16) __half g_kh[NB * NH * SEQ * DH];
__device__ __align__(16) __half g_vh[NB * NH * SEQ * DH];
__device__ float g_vsum[NB * NH * DH];
__device__ __align__(16) float g_padf[NB * SEQ];

// ---------------- PTX helpers ----------------
__device__ __forceinline__ uint32_t smem_u32(const void* p) {
    return (uint32_t)__cvta_generic_to_shared(p);
}
__device__ __forceinline__ void cp16(uint32_t dst, const void* src) {
    asm volatile("cp.async.cg.shared.global [%0], [%1], 16;" :: "r"(dst), "l"(src));
}
__device__ __forceinline__ void cp4(uint32_t dst, const void* src) {
    asm volatile("cp.async.ca.shared.global [%0], [%1], 4;" :: "r"(dst), "l"(src));
}
__device__ __forceinline__ void cp_commit() { asm volatile("cp.async.commit_group;"); }
template <int N>
__device__ __forceinline__ void cp_wait() { asm volatile("cp.async.wait_group %0;" :: "n"(N)); }

__device__ __forceinline__ void ldsm_x4(uint32_t& r0, uint32_t& r1, uint32_t& r2, uint32_t& r3,
                                        uint32_t addr) {
    asm volatile("ldmatrix.sync.aligned.m8n8.x4.shared.b16 {%0,%1,%2,%3}, [%4];"
                 : "=r"(r0), "=r"(r1), "=r"(r2), "=r"(r3) : "r"(addr));
}
__device__ __forceinline__ void ldsm_x4_t(uint32_t& r0, uint32_t& r1, uint32_t& r2, uint32_t& r3,
                                          uint32_t addr) {
    asm volatile("ldmatrix.sync.aligned.m8n8.x4.trans.shared.b16 {%0,%1,%2,%3}, [%4];"
                 : "=r"(r0), "=r"(r1), "=r"(r2), "=r"(r3) : "r"(addr));
}
__device__ __forceinline__ void mma_16816(float* c, const uint32_t* a, uint32_t b0, uint32_t b1) {
    asm volatile(
        "mma.sync.aligned.m16n8k16.row.col.f32.f16.f16.f32 "
        "{%0,%1,%2,%3},{%4,%5,%6,%7},{%8,%9},{%0,%1,%2,%3};"
        : "+f"(c[0]), "+f"(c[1]), "+f"(c[2]), "+f"(c[3])
        : "r"(a[0]), "r"(a[1]), "r"(a[2]), "r"(a[3]), "r"(b0), "r"(b1));
}
__device__ __forceinline__ uint32_t pack_h2(float x, float y) {
    __half2 h = __floats2half2_rn(x, y);
    return *reinterpret_cast<uint32_t*>(&h);
}
__device__ __forceinline__ float ex2f(float x) {
    float y;
    asm("ex2.approx.ftz.f32 %0, %1;" : "=f"(y) : "f"(x));
    return y;
}

#define QSCALE (0.125f * 1.44269504f)  // 1/sqrt(64) * log2(e), folded into Wq/bq

// ---------------- fp32 -> fp16 conversion (X, W; Wq folds scale); pad -> float ----------------
__global__ void cvt_kernel(const float* __restrict__ q, const float* __restrict__ k,
                           const float* __restrict__ v, const float* __restrict__ Wq,
                           const float* __restrict__ Wk, const float* __restrict__ Wv,
                           const int* __restrict__ pad) {
    const int y = blockIdx.y;
    if (y == 6) {
        for (int i = blockIdx.x * blockDim.x + threadIdx.x; i < NB * SEQ;
             i += gridDim.x * blockDim.x)
            g_padf[i] = pad[i] ? 1.0f : 0.0f;
        return;
    }
    const float* src;
    __half* dst;
    int n4;
    float sc = 1.0f;
    switch (y) {
        case 0: src = q;  dst = g_xh;           n4 = XSZ / 4; break;
        case 1: src = k;  dst = g_xh + XSZ;     n4 = XSZ / 4; break;
        case 2: src = v;  dst = g_xh + 2 * XSZ; n4 = XSZ / 4; break;
        case 3: src = Wq; dst = g_wh;           n4 = WSZ / 4; sc = QSCALE; break;
        case 4: src = Wk; dst = g_wh + WSZ;     n4 = WSZ / 4; break;
        default: src = Wv; dst = g_wh + 2 * WSZ; n4 = WSZ / 4; break;
    }
    for (int i = blockIdx.x * blockDim.x + threadIdx.x; i < n4; i += gridDim.x * blockDim.x) {
        float4 f = ((const float4*)src)[i];
        __half2 h0 = __floats2half2_rn(f.x * sc, f.y * sc);
        __half2 h1 = __floats2half2_rn(f.z * sc, f.w * sc);
        uint2 u;
        u.x = *(uint32_t*)&h0;
        u.y = *(uint32_t*)&h1;
        ((uint2*)dst)[i] = u;
    }
}

// ---------------- QKV projection GEMM (half in, cp.async, 4 small CTAs/SM) ----------------
// Out[m, j] = X[m, :] . W[j, :] + bias[j]
// BM=64, BN=128, BK=64, 128 threads, 4 warps in 2(m) x 2(n), warp tile 32x64.
__global__ __launch_bounds__(128, 4) void qkv_proj_kernel(
    const float* __restrict__ bq, const float* __restrict__ bk, const float* __restrict__ bv)
{
    const int z = blockIdx.z;
    const __half* X   = g_xh + (size_t)z * XSZ;
    const __half* W   = g_wh + (size_t)z * WSZ;
    const float* bias = (z == 0) ? bq : (z == 1) ? bk : bv;
    __half* Out       = (z == 0) ? g_qh : (z == 1) ? g_kh : g_vh;
    const float wsc   = (z == 0) ? QSCALE : 1.0f;

    __shared__ __align__(16) __half As[2][64][72];
    __shared__ __align__(16) __half Bs[2][128][72];

    const int tid = threadIdx.x, lane = tid & 31, wid = tid >> 5;
    const int wm = wid >> 1;   // 0..1 -> rows wm*32
    const int wn = wid & 1;    // 0..1 -> cols wn*64
    const int bm = blockIdx.x * 64;
    const int bn = blockIdx.y * 128;

    float c[2][8][4] = {};

    // A: 64 rows x 8 chunks = 512 chunks (4/thread). B: 128 rows x 8 = 1024 (8/thread).
#define QKV_LOAD(buf, k0)                                                            \
    {                                                                                \
        _Pragma("unroll") for (int i = 0; i < 4; i++) {                              \
            int cid = i * 128 + tid;                                                 \
            int r = cid >> 3, c8 = cid & 7;                                          \
            cp16(smem_u32(&As[buf][r][c8 * 8]),                                      \
                 X + (size_t)(bm + r) * EDIM + (k0) + c8 * 8);                       \
        }                                                                            \
        _Pragma("unroll") for (int i = 0; i < 8; i++) {                              \
            int cid = i * 128 + tid;                                                 \
            int r = cid >> 3, c8 = cid & 7;                                          \
            cp16(smem_u32(&Bs[buf][r][c8 * 8]),                                      \
                 W + (size_t)(bn + r) * EDIM + (k0) + c8 * 8);                       \
        }                                                                            \
    }

    QKV_LOAD(0, 0);
    cp_commit();

    int cur = 0;
    for (int k0 = 0; k0 < EDIM; k0 += 64) {
        cp_wait<0>();
        __syncthreads();
        if (k0 + 64 < EDIM) {
            QKV_LOAD(cur ^ 1, k0 + 64);
            cp_commit();
        }

#pragma unroll
        for (int ks = 0; ks < 4; ks++) {
            uint32_t af[2][4], bf[4][4];
#pragma unroll
            for (int mi = 0; mi < 2; mi++) {
                uint32_t a = smem_u32(&As[cur][wm * 32 + mi * 16 + (lane & 15)]
                                            [ks * 16 + ((lane >> 4) & 1) * 8]);
                ldsm_x4(af[mi][0], af[mi][1], af[mi][2], af[mi][3], a);
            }
#pragma unroll
            for (int np = 0; np < 4; np++) {
                int nr = wn * 64 + np * 16 + (lane & 7) + ((lane >> 4) & 1) * 8;
                int nc = ks * 16 + ((lane >> 3) & 1) * 8;
                uint32_t a = smem_u32(&Bs[cur][nr][nc]);
                ldsm_x4(bf[np][0], bf[np][1], bf[np][2], bf[np][3], a);
            }
#pragma unroll
            for (int mi = 0; mi < 2; mi++)
#pragma unroll
                for (int ni = 0; ni < 8; ni++)
                    mma_16816(c[mi][ni], af[mi],
                              bf[ni >> 1][(ni & 1) * 2], bf[ni >> 1][(ni & 1) * 2 + 1]);
        }
        cur ^= 1;
    }

    const int g = lane >> 2, t4 = lane & 3;
#pragma unroll
    for (int mi = 0; mi < 2; mi++) {
#pragma unroll
        for (int ni = 0; ni < 8; ni++) {
            int col = bn + wn * 64 + ni * 8 + t4 * 2;
            float b0 = bias[col] * wsc, b1 = bias[col + 1] * wsc;
            int hh = col >> 6, d = col & 63;
#pragma unroll
            for (int hr = 0; hr < 2; hr++) {
                int row = bm + wm * 32 + mi * 16 + g + hr * 8;
                int bb = row >> 11, srow = row & 2047;
                __half2 hv = __floats2half2_rn(c[mi][ni][hr * 2] + b0, c[mi][ni][hr * 2 + 1] + b1);
                *(__half2*)(Out + ((size_t)((bb * NH + hh) * SEQ + srow)) * DH + d) = hv;
            }
        }
    }
}

// ---------------- V column mean (for fully-masked rows) ----------------
__global__ void vsum_kernel() {
    const int bh = blockIdx.x;
    const int rg = threadIdx.x >> 3;
    const int dc = threadIdx.x & 7;
    const __half* p = g_vh + (size_t)bh * SEQ * DH;
    float acc[8] = {};
#pragma unroll 4
    for (int r = rg; r < SEQ; r += 32) {
        uint4 u = *(const uint4*)(p + (size_t)r * DH + dc * 8);
        const __half2* h = (const __half2*)&u;
#pragma unroll
        for (int j = 0; j < 4; j++) {
            float2 f = __half22float2(h[j]);
            acc[2 * j] += f.x;
            acc[2 * j + 1] += f.y;
        }
    }
    __shared__ float red[32][64];
#pragma unroll
    for (int j = 0; j < 8; j++) red[rg][dc * 8 + j] = acc[j];
    __syncthreads();
    if (threadIdx.x < 64) {
        float s = 0.f;
#pragma unroll
        for (int i = 0; i < 32; i++) s += red[i][threadIdx.x];
        g_vsum[bh * DH + threadIdx.x] = s * (1.0f / SEQ);
    }
}

// ---------------- Flash attention (paired row-blocks, 4-warp CTAs; proven R14 form) ----------------
// grid (16, H, N), 128 threads (4 warps x 16 rows). Br=64, Bc=64, D=64.
// Paired row-blocks {x, 31-x} -> constant 33 tiles/CTA, single wave at 4 CTA/SM.
// Loop schedule: [wait<0>; sync; issue KV(jb+1); compute jb].
#define NRB64 (SEQ / 64)
__global__ __launch_bounds__(128, 4) void flash_kernel(float* __restrict__ out)
{
    const int h = blockIdx.y, b = blockIdx.z;
    const int tid = threadIdx.x, lane = tid & 31, warp = tid >> 5;

    const __half* Kg = g_kh + (size_t)((b * NH + h) * SEQ) * DH;
    const __half* Vg = g_vh + (size_t)((b * NH + h) * SEQ) * DH;
    const float* padf = g_padf + b * SEQ;

    __shared__ __align__(16) __half Qs[64][72];
    __shared__ __align__(16) __half Ks[2][64][72];
    __shared__ __align__(16) __half Vs[2][64][72];
    __shared__ __align__(16) float pads[2][64];

#define FLASH_LOAD_KV(buf, jb)                                                       \
    {                                                                                \
        _Pragma("unroll") for (int i = 0; i < 4; i++) {                              \
            int cid = i * 128 + tid;                                                 \
            int r = cid >> 3, c8 = cid & 7;                                          \
            cp16(smem_u32(&Ks[buf][r][c8 * 8]),                                      \
                 Kg + (size_t)((jb) * 64 + r) * DH + c8 * 8);                        \
            cp16(smem_u32(&Vs[buf][r][c8 * 8]),                                      \
                 Vg + (size_t)((jb) * 64 + r) * DH + c8 * 8);                        \
        }                                                                            \
        if (tid < 64) cp4(smem_u32(&pads[buf][tid]), padf + (jb) * 64 + tid);        \
    }

    const int g = lane >> 2, t4 = lane & 3;

#pragma unroll 1
    for (int pass = 0; pass < 2; pass++) {
        const int rb = pass == 0 ? (int)blockIdx.x : (NRB64 - 1 - (int)blockIdx.x);
        const __half* Qg = g_qh + ((size_t)((b * NH + h) * SEQ) + rb * 64) * DH;

        // prologue: Q tile + KV tile 0, one commit group
#pragma unroll
        for (int i = 0; i < 4; i++) {
            int cid = i * 128 + tid;
            int r = cid >> 3, c8 = cid & 7;
            cp16(smem_u32(&Qs[r][c8 * 8]), Qg + (size_t)r * DH + c8 * 8);
        }
        FLASH_LOAD_KV(0, 0);
        cp_commit();

        uint32_t qf[4][4];
        float of[8][4] = {};
        float l0 = 0.f, l1 = 0.f;
        const int row0 = rb * 64 + warp * 16 + g;
        const int row1 = row0 + 8;
        const int jbmax = rb;

        for (int jb = 0; jb <= jbmax; jb++) {
            const int cur = jb & 1;

            cp_wait<0>();
            __syncthreads();
            if (jb < jbmax) {
                FLASH_LOAD_KV(cur ^ 1, jb + 1);
                cp_commit();
            }
            if (jb == 0) {
#pragma unroll
                for (int kk = 0; kk < 4; kk++) {
                    uint32_t a = smem_u32(&Qs[warp * 16 + (lane & 15)]
                                             [kk * 16 + ((lane >> 4) & 1) * 8]);
                    ldsm_x4(qf[kk][0], qf[kk][1], qf[kk][2], qf[kk][3], a);
                }
            }

            // S = Q K^T
            float sf[8][4] = {};
#pragma unroll
            for (int kk = 0; kk < 4; kk++) {
                uint32_t kb[4][4];
#pragma unroll
                for (int np = 0; np < 4; np++) {
                    int nr = np * 16 + (lane & 7) + ((lane >> 4) & 1) * 8;
                    int nc = kk * 16 + ((lane >> 3) & 1) * 8;
                    uint32_t a = smem_u32(&Ks[cur][nr][nc]);
                    ldsm_x4(kb[np][0], kb[np][1], kb[np][2], kb[np][3], a);
                }
#pragma unroll
                for (int nt = 0; nt < 8; nt++)
                    mma_16816(sf[nt], qf[kk],
                              kb[nt >> 1][(nt & 1) * 2], kb[nt >> 1][(nt & 1) * 2 + 1]);
            }

            // e = 2^s * pad; causal select only on the diagonal tile
            if (jb == jbmax) {
#pragma unroll
                for (int nt = 0; nt < 8; nt++) {
                    int cloc = nt * 8 + t4 * 2;
                    int tc = jb * 64 + cloc;
                    float2 pp = *(const float2*)&pads[cur][cloc];
                    float e0 = (tc     <= row0) ? ex2f(sf[nt][0]) * pp.x : 0.f;
                    float e1 = (tc + 1 <= row0) ? ex2f(sf[nt][1]) * pp.y : 0.f;
                    float e2 = (tc     <= row1) ? ex2f(sf[nt][2]) * pp.x : 0.f;
                    float e3 = (tc + 1 <= row1) ? ex2f(sf[nt][3]) * pp.y : 0.f;
                    l0 += e0 + e1; l1 += e2 + e3;
                    sf[nt][0] = e0; sf[nt][1] = e1; sf[nt][2] = e2; sf[nt][3] = e3;
                }
            } else {
#pragma unroll
                for (int nt = 0; nt < 8; nt++) {
                    int cloc = nt * 8 + t4 * 2;
                    float2 pp = *(const float2*)&pads[cur][cloc];
                    float e0 = ex2f(sf[nt][0]) * pp.x;
                    float e1 = ex2f(sf[nt][1]) * pp.y;
                    float e2 = ex2f(sf[nt][2]) * pp.x;
                    float e3 = ex2f(sf[nt][3]) * pp.y;
                    l0 += e0 + e1; l1 += e2 + e3;
                    sf[nt][0] = e0; sf[nt][1] = e1; sf[nt][2] = e2; sf[nt][3] = e3;
                }
            }

            // P as A-fragment (FA2 trick)
            uint32_t pf[4][4];
#pragma unroll
            for (int kk = 0; kk < 4; kk++) {
                pf[kk][0] = pack_h2(sf[2 * kk][0],     sf[2 * kk][1]);
                pf[kk][1] = pack_h2(sf[2 * kk][2],     sf[2 * kk][3]);
                pf[kk][2] = pack_h2(sf[2 * kk + 1][0], sf[2 * kk + 1][1]);
                pf[kk][3] = pack_h2(sf[2 * kk + 1][2], sf[2 * kk + 1][3]);
            }

            // O += P V
#pragma unroll
            for (int kk = 0; kk < 4; kk++) {
                uint32_t vb[4][4];
#pragma unroll
                for (int np = 0; np < 4; np++) {
                    int vr = kk * 16 + (lane & 7) + ((lane >> 3) & 1) * 8;
                    int vc = np * 16 + ((lane >> 4) & 1) * 8;
                    uint32_t a = smem_u32(&Vs[cur][vr][vc]);
                    ldsm_x4_t(vb[np][0], vb[np][1], vb[np][2], vb[np][3], a);
                }
#pragma unroll
                for (int nt = 0; nt < 8; nt++)
                    mma_16816(of[nt], pf[kk],
                              vb[nt >> 1][(nt & 1) * 2], vb[nt >> 1][(nt & 1) * 2 + 1]);
            }
        }

        l0 += __shfl_xor_sync(0xffffffffu, l0, 1);
        l0 += __shfl_xor_sync(0xffffffffu, l0, 2);
        l1 += __shfl_xor_sync(0xffffffffu, l1, 1);
        l1 += __shfl_xor_sync(0xffffffffu, l1, 2);

        bool fm0 = (l0 == 0.f), fm1 = (l1 == 0.f);  // fully masked row -> uniform over all T
        float inv0 = fm0 ? 0.f : 1.f / l0;
        float inv1 = fm1 ? 0.f : 1.f / l1;
        const float* vs = g_vsum + (b * NH + h) * DH;
#pragma unroll
        for (int nt = 0; nt < 8; nt++) {
            int d = nt * 8 + t4 * 2;
            float o0 = of[nt][0] * inv0, o1 = of[nt][1] * inv0;
            float o2 = of[nt][2] * inv1, o3 = of[nt][3] * inv1;
            if (fm0) { o0 = vs[d]; o1 = vs[d + 1]; }
            if (fm1) { o2 = vs[d]; o3 = vs[d + 1]; }
            size_t base0 = ((size_t)b * SEQ + row0) * EDIM + h * DH + d;
            size_t base1 = ((size_t)b * SEQ + row1) * EDIM + h * DH + d;
            *(float2*)(out + base0) = make_float2(o0, o1);
            *(float2*)(out + base1) = make_float2(o2, o3);
        }
        __syncthreads();  // protect smem before next pass's prologue loads
    }
}

// ---------------- launch ----------------
extern "C" void kernel_launch(void* const* d_in, const int* in_sizes, int n_in,
                              void* d_out, int out_size) {
    const float* query = (const float*)d_in[0];
    const float* key   = (const float*)d_in[1];
    const float* value = (const float*)d_in[2];
    const int*   pad   = (const int*)d_in[3];
    // d_in[4] = subsq_mask (tril) -> implemented as causal predicate
    const float* Wq = (const float*)d_in[5];
    const float* bq = (const float*)d_in[6];
    const float* Wk = (const float*)d_in[7];
    const float* bk = (const float*)d_in[8];
    const float* Wv = (const float*)d_in[9];
    const float* bv = (const float*)d_in[10];
    float* out = (float*)d_out;

    cvt_kernel<<<dim3(512, 7), 256>>>(query, key, value, Wq, Wk, Wv, pad);
    qkv_proj_kernel<<<dim3(64, 8, 3), 128>>>(bq, bk, bv);
    vsum_kernel<<<NB * NH, 256>>>();
    flash_kernel<<<dim3(NRB64 / 2, NH, NB), 128>>>(out);
}